// round 1
// baseline (speedup 1.0000x reference)
#include <cuda_runtime.h>
#include <math.h>

// Blobber: out = sigmoid((box3x3(sigmoid((box3x3(in) - 0.01)*1000)) - 0.9)*1000)
// (the reference's 4 iterations are identical — each re-reads `inputs` — so one
//  iteration suffices). Fully fused single pass, smem-tiled.

#define IMG     512
#define TS      32          // output tile
#define IN_S    (TS + 4)    // 36: input halo region (two stacked 3x3 convs => radius 2)
#define MID_S   (TS + 2)    // 34: intermediate halo region (radius 1)
#define NTHREADS 256

__device__ __forceinline__ float sigmoidf_(float z) {
    return 1.0f / (1.0f + expf(-z));
}

__global__ __launch_bounds__(NTHREADS)
void blobber_fused_kernel(const float* __restrict__ in, float* __restrict__ out) {
    __shared__ float s_in[IN_S][IN_S + 1];     // +1 pad to dodge bank conflicts
    __shared__ float s_mid[MID_S][MID_S + 2];

    const int tid = threadIdx.x;
    const int bx = blockIdx.x * TS;
    const int by = blockIdx.y * TS;
    const int b  = blockIdx.z;

    const float* img  = in  + (size_t)b * IMG * IMG;
    float*       oimg = out + (size_t)b * IMG * IMG;

    // ---- stage 0: load 36x36 input halo (zero-padded at image borders) ----
    #pragma unroll
    for (int i = tid; i < IN_S * IN_S; i += NTHREADS) {
        int r = i / IN_S, c = i % IN_S;
        int gr = by + r - 2;
        int gc = bx + c - 2;
        float v = 0.0f;
        if ((unsigned)gr < (unsigned)IMG && (unsigned)gc < (unsigned)IMG)
            v = img[gr * IMG + gc];
        s_in[r][c] = v;
    }
    __syncthreads();

    const float w = 1.0f / 9.0f;

    // ---- stage 1: first conv + sigmoid -> 34x34 intermediate ----
    // mid pixel (r,c) is image coord (by+r-1, bx+c-1); must be EXACT 0 when
    // outside the image (second conv's zero padding pads the sigmoid map).
    #pragma unroll
    for (int i = tid; i < MID_S * MID_S; i += NTHREADS) {
        int r = i / MID_S, c = i % MID_S;
        int gr = by + r - 1;
        int gc = bx + c - 1;
        float v = 0.0f;
        if ((unsigned)gr < (unsigned)IMG && (unsigned)gc < (unsigned)IMG) {
            float s = 0.0f;
            #pragma unroll
            for (int dy = 0; dy < 3; dy++)
                #pragma unroll
                for (int dx = 0; dx < 3; dx++)
                    s += s_in[r + dy][c + dx];
            v = sigmoidf_((s * w - 0.01f) * 1000.0f);
        }
        s_mid[r][c] = v;
    }
    __syncthreads();

    // ---- stage 2: second conv + sigmoid -> 32x32 output ----
    #pragma unroll
    for (int i = tid; i < TS * TS; i += NTHREADS) {
        int r = i / TS, c = i % TS;
        float s = 0.0f;
        #pragma unroll
        for (int dy = 0; dy < 3; dy++)
            #pragma unroll
            for (int dx = 0; dx < 3; dx++)
                s += s_mid[r + dy][c + dx];
        float v = sigmoidf_((s * w - 0.9f) * 1000.0f);
        oimg[(size_t)(by + r) * IMG + (bx + c)] = v;
    }
}

extern "C" void kernel_launch(void* const* d_in, const int* in_sizes, int n_in,
                              void* d_out, int out_size) {
    const float* in = (const float*)d_in[0];
    float* out = (float*)d_out;
    dim3 grid(IMG / TS, IMG / TS, 32);   // (16,16,32)
    blobber_fused_kernel<<<grid, NTHREADS>>>(in, out);
}